// round 9
// baseline (speedup 1.0000x reference)
#include <cuda_runtime.h>
#include <cuda_bf16.h>

// HOG layer, fully fused:
//   sobel(3x3, zero pad) -> mag/angle -> 10-bin soft histogram -> 8x8 mean pool
// x: (16,1,512,512) f32   out: (16,10,64,64) f32
//
// Grid: (64 pooled rows, 16 images), 128 threads/CTA (single wave at 8 CTA/SM).
// Thread t: cell = t>>1 (8 input cols), sub = t&1 (4 input rows).
//
// Binning: fast comparator classifier (4 tan-boundary compares) with a
// double-threshold guard band (+-1e-3). Pixels inside the band (or near an
// axis) take the exact reference path: atan2f (same libdevice __nv_atan2f
// XLA calls), phase/pi_f32*10, floor/ceil, mod 10. Outside the band the
// comparator bin provably equals the reference bin (atan2f err << band).
//
// Tile layout: stored offset f(s) = s + (s>>3)  (s = 1 + col, halo at s=0/513),
// row stride 580. Window col jj of cell c reads s = 8c + jj (jj=0 is the w-1
// column), i.e. f = 9c + jj + (jj>=8 ? 1 : 0).   [R8 fix: previous rounds used
// s = 8c+1+jj -- a one-column shift plus an OOB-garbage read at cell 63, which
// produced the rel_err 2.67e-1 failure.]
// Lane bank = 9*(cellInWarp) + 16*sub + const (mod 32); 9 invertible mod 32 and
// 9*da = 16 (mod 32) has no solution with |da|<16 -> all 32 lanes distinct ->
// conflict-free column reads.
// Histogram: column-major hist[bin*128 + tid] (bank = tid mod 32) ->
// conflict-free scatter for arbitrary per-lane bins.

#define R_STRIDE 580
#define NT       128
#define PI_F     3.14159274f   // float32 rounding of np.pi

// tan(k*pi/10) scaled by (1 -+ 1e-3): guard band around each bin boundary
#define T1_LO 0.32459478f
#define T1_HI 0.32524462f
#define T2_LO 0.72581599f
#define T2_HI 0.72726907f
#define T3_LO 1.37500552f
#define T3_HI 1.37775828f
#define T4_LO 3.07460586f
#define T4_HI 3.08076122f
#define AX_EPS 1.0e-3f

__device__ __forceinline__ float fast_sqrtf(float v)
{
    float r;
    asm("sqrt.approx.f32 %0, %1;" : "=f"(r) : "f"(v));
    return r;
}

__device__ __forceinline__ void accum_pixel(float gx, float gy, float* __restrict__ hcol)
{
    float mag = fast_sqrtf(fmaf(gx, gx, gy * gy));

    // Direction mod pi: flip so the atan2 y-argument (gx) is >= 0.
    float uu = (gx < 0.0f) ? -gy : gy;
    float vv = fabsf(gx);
    float au = fabsf(uu);

    // Two-sided comparator: if both agree and we're away from the axes,
    // the bin is unambiguous (identical to reference atan2-based bin).
    int jlo = (vv > au * T1_HI) + (vv > au * T2_HI) +
              (vv > au * T3_HI) + (vv > au * T4_HI);
    int jhi = (vv > au * T1_LO) + (vv > au * T2_LO) +
              (vv > au * T3_LO) + (vv > au * T4_LO);

    int fl, ce;
    if (jlo == jhi && vv > au * AX_EPS && au > vv * AX_EPS) {
        fl = (uu >= 0.0f) ? jlo : 9 - jlo;   // floor bin 0..9
        ce = (fl == 9) ? 0 : fl + 1;         // ceil bin (wraps)
    } else {
        // Rare path (~0.2% of pixels): exact reference arithmetic.
        float phase = atan2f(gx, gy);
        float pif   = phase / PI_F * 10.0f;
        fl = (int)floorf(pif);
        ce = (int)ceilf(pif);
        fl %= 10; if (fl < 0) fl += 10;
        ce %= 10; if (ce < 0) ce += 10;
    }

    hcol[fl * NT] += mag;
    hcol[ce * NT] += 1.0f - mag;
}

// Load one stored column (6 tile rows) and form separable sobel terms for
// 4 pixel rows: A[r] = t_r + 2t_{r+1} + t_{r+2},  C[r] = t_r - t_{r+2}.
__device__ __forceinline__ void load_col6(const float* __restrict__ tile, int off,
                                          float* __restrict__ A, float* __restrict__ C)
{
    float t0 = tile[off];
    float t1 = tile[off + 1 * R_STRIDE];
    float t2 = tile[off + 2 * R_STRIDE];
    float t3 = tile[off + 3 * R_STRIDE];
    float t4 = tile[off + 4 * R_STRIDE];
    float t5 = tile[off + 5 * R_STRIDE];
    A[0] = t0 + 2.0f * t1 + t2;
    A[1] = t1 + 2.0f * t2 + t3;
    A[2] = t2 + 2.0f * t3 + t4;
    A[3] = t3 + 2.0f * t4 + t5;
    C[0] = t0 - t2;
    C[1] = t1 - t3;
    C[2] = t2 - t4;
    C[3] = t3 - t5;
}

__global__ __launch_bounds__(NT, 8) void hog_fused_kernel(
    const float* __restrict__ x, float* __restrict__ out)
{
    __shared__ float tile[10 * R_STRIDE];   // 23200 B
    __shared__ float hist[10 * NT];         //  5120 B, column-major [bin][tid]

    const int tid = threadIdx.x;
    const int py  = blockIdx.x;   // pooled row 0..63
    const int n   = blockIdx.y;   // image 0..15

    // zero this thread's histogram column (conflict-free)
    #pragma unroll
    for (int b = 0; b < 10; b++) hist[b * NT + tid] = 0.0f;

    // zero halo columns: stored offsets f(0)=0 and f(513)=577, all 10 rows
    if (tid < 20) {
        int tr = tid >> 1;
        tile[tr * R_STRIDE + ((tid & 1) ? 577 : 0)] = 0.0f;
    }

    // stage input rows py*8-1 .. py*8+8 (zero outside image), float4 loads;
    // iteration tr loads tile row tr, thread tid handles float4 column tid.
    const float4* __restrict__ xin4 =
        (const float4*)(x + (size_t)n * (512 * 512));
    #pragma unroll
    for (int tr = 0; tr < 10; tr++) {
        int g = py * 8 - 1 + tr;          // global row
        float4 v = make_float4(0.0f, 0.0f, 0.0f, 0.0f);
        if ((unsigned)g < 512u) v = xin4[g * 128 + tid];
        float* rowp = &tile[tr * R_STRIDE];
        int s = tid * 4 + 1;              // stored col s, pad via f(s)=s+(s>>3)
        rowp[s + (s >> 3)]             = v.x;
        rowp[(s + 1) + ((s + 1) >> 3)] = v.y;
        rowp[(s + 2) + ((s + 2) >> 3)] = v.z;
        rowp[(s + 3) + ((s + 3) >> 3)] = v.w;
    }
    __syncthreads();

    const int cell = tid >> 1;        // 0..63
    const int sub  = tid & 1;         // 0..1
    const int r0   = sub * 4;         // first tile row used (4 pixel rows/thread)
    float* __restrict__ hcol = &hist[tid];

    // Stored offset of (tile row r0+r, window col jj):
    //   s = 8*cell + jj  (jj=0 -> the w-1 column of the cell's first pixel)
    //   f(s) = 9*cell + jj + (jj >= 8 ? 1 : 0)
    const int base = r0 * R_STRIDE + 9 * cell;

    // Sliding 3-column window: p = col(w-1), c = col(w), n = col(w+1)
    float Ap[4], Cp[4], Ac[4], Cc[4], An[4], Cn[4];
    load_col6(tile, base + 0, Ap, Cp);
    load_col6(tile, base + 1, Ac, Cc);

    #pragma unroll
    for (int i = 0; i < 8; i++) {
        const int jj = i + 2;                         // incoming column 2..9
        load_col6(tile, base + jj + (jj >= 8 ? 1 : 0), An, Cn);

        // gx = colA(w-1) - colA(w+1); gy = colC(w-1) + 2*colC(w) + colC(w+1)
        #pragma unroll
        for (int r = 0; r < 4; r++) {
            float gx = Ap[r] - An[r];
            float gy = Cp[r] + 2.0f * Cc[r] + Cn[r];
            accum_pixel(gx, gy, hcol);
        }

        #pragma unroll
        for (int r = 0; r < 4; r++) {
            Ap[r] = Ac[r]; Cp[r] = Cc[r];
            Ac[r] = An[r]; Cc[r] = Cn[r];
        }
    }
    __syncthreads();

    // Reduce 2 sub-threads per cell, scale by 1/64, write coalesced:
    // out[n*40960 + b*4096 + py*64 + c]
    float* __restrict__ o = out + ((size_t)(n * 10) * 64 + py) * 64;
    #pragma unroll
    for (int it = 0; it < 5; it++) {
        int idx = tid + it * NT;    // 0..639
        int b = idx >> 6;           // bin 0..9
        int c = idx & 63;           // cell
        const float* h = &hist[b * NT + c * 2];
        o[(size_t)b * (64 * 64) + c] = (h[0] + h[1]) * (1.0f / 64.0f);
    }
}

extern "C" void kernel_launch(void* const* d_in, const int* in_sizes, int n_in,
                              void* d_out, int out_size)
{
    const float* x = (const float*)d_in[0];
    float* out     = (float*)d_out;
    dim3 grid(64, 16);
    hog_fused_kernel<<<grid, NT>>>(x, out);
}

// round 12
// speedup vs baseline: 1.0970x; 1.0970x over previous
#include <cuda_runtime.h>
#include <cuda_bf16.h>

// HOG layer, fully fused:
//   sobel(3x3, zero pad) -> mag/angle -> 10-bin soft histogram -> 8x8 mean pool
// x: (16,1,512,512) f32   out: (16,10,64,64) f32
//
// Half-width CTAs for occupancy. Grid (128,16): blockIdx.x = py*2+half,
// each CTA covers 32 cells (256 input cols + 1-col halo each side) x 8 rows.
// 128 threads: cell = tid>>2 (8 cols), sub = tid&3 (2 pixel rows).
// smem ~17.3KB/CTA, launch_bounds(128,11) -> 46-reg cap (no hot-loop spill
// risk; 12 CTAs' 42-reg cap was borderline) -> ~44 warps/SM resident vs 26 in
// the R9 version, where ncu showed occupancy was binding (issue 58%, L1 22%).
//
// Binning: ratio comparator t = |gx|/|uu| via __fdividef, compared against
// tan(k*pi/10)*(1-+1e-3) guard-banded thresholds (immediate compares, no FMULs).
// Ambiguous/axis/NaN pixels (~0.2%) take the exact reference path (noinline):
// atan2f, phase/pi_f32*10, floor/ceil, mod 10. Outside the band the comparator
// bin provably equals the reference bin (rcp+atan2f err << 1e-3 band).
//
// Tile: stored col s in 0..257 (s=0 left halo, s=1+local col, s=257 right halo),
// f(s) = s + (s>>3), row stride 292 (== 4 mod 16). Column-read bank =
// 9*cellInWarp + 8*sub + const (mod 32): enumerating c in 0..7, s in 0..3 gives
// all 32 residues -> conflict-free.
// Histogram: column-major hist[bin*128 + tid] (128 == 0 mod 32) -> conflict-free
// scatter; 11 columns so fast-path ce = fl+1 needs no wrap (col 10 folded to 0).

#define R_STRIDE 292
#define NT       128
#define PI_F     3.14159274f   // float32 rounding of np.pi

// tan(k*pi/10) scaled by (1 -+ 1e-3): guard band around each bin boundary
#define T1_LO 0.32459478f
#define T1_HI 0.32524462f
#define T2_LO 0.72581599f
#define T2_HI 0.72726907f
#define T3_LO 1.37500552f
#define T3_HI 1.37775828f
#define T4_LO 3.07460586f
#define T4_HI 3.08076122f
#define AX_EPS 1.0e-3f
#define AX_MAX 1.0e3f

__device__ __forceinline__ float fast_sqrtf(float v)
{
    float r;
    asm("sqrt.approx.f32 %0, %1;" : "=f"(r) : "f"(v));
    return r;
}

// Exact reference-arithmetic binning (rare path; emitted once, not per call site).
__device__ __noinline__ int2 ref_bins(float gx, float gy)
{
    float phase = atan2f(gx, gy);
    float pif   = phase / PI_F * 10.0f;
    int fl = (int)floorf(pif);
    int ce = (int)ceilf(pif);
    fl %= 10; if (fl < 0) fl += 10;
    ce %= 10; if (ce < 0) ce += 10;
    return make_int2(fl, ce);
}

__device__ __forceinline__ void accum_pixel(float gx, float gy, float* __restrict__ hcol)
{
    float mag = fast_sqrtf(fmaf(gx, gx, gy * gy));

    // Direction mod pi: flip so the atan2 y-argument (gx) is >= 0.
    float uu = (gx < 0.0f) ? -gy : gy;
    float vv = fabsf(gx);
    float au = fabsf(uu);
    float t  = __fdividef(vv, au);   // approx; err << guard band

    // Two-sided comparator on the ratio (immediate-operand compares).
    int jlo = (t > T1_HI) + (t > T2_HI) + (t > T3_HI) + (t > T4_HI);
    int jhi = (t > T1_LO) + (t > T2_LO) + (t > T3_LO) + (t > T4_LO);

    int fl, ce;
    if (jlo == jhi && t >= AX_EPS && t <= AX_MAX) {   // NaN-safe: NaN -> fallback
        fl = (uu >= 0.0f) ? jlo : 9 - jlo;   // floor bin 0..9
        ce = fl + 1;                         // col 10 folded into bin 0 later
    } else {
        int2 b = ref_bins(gx, gy);           // ~0.2% of pixels
        fl = b.x; ce = b.y;
    }

    hcol[fl * NT] += mag;
    hcol[ce * NT] += 1.0f - mag;
}

// Load one stored column (4 tile rows) and form separable sobel terms for
// 2 pixel rows: A[r] = t_r + 2t_{r+1} + t_{r+2},  C[r] = t_r - t_{r+2}.
__device__ __forceinline__ void load_col4(const float* __restrict__ tile, int off,
                                          float& A0, float& A1, float& C0, float& C1)
{
    float t0 = tile[off];
    float t1 = tile[off + 1 * R_STRIDE];
    float t2 = tile[off + 2 * R_STRIDE];
    float t3 = tile[off + 3 * R_STRIDE];
    A0 = t0 + 2.0f * t1 + t2;
    A1 = t1 + 2.0f * t2 + t3;
    C0 = t0 - t2;
    C1 = t1 - t3;
}

__global__ __launch_bounds__(NT, 11) void hog_fused_kernel(
    const float* __restrict__ x, float* __restrict__ out)
{
    __shared__ float tile[10 * R_STRIDE];   // 11680 B
    __shared__ float hist[11 * NT];         //  5632 B, column-major [bin][tid]

    const int tid  = threadIdx.x;
    const int py   = blockIdx.x >> 1;   // pooled row 0..63
    const int half = blockIdx.x & 1;    // column half 0..1
    const int n    = blockIdx.y;        // image 0..15

    // zero this thread's histogram column (conflict-free)
    #pragma unroll
    for (int b = 0; b < 11; b++) hist[b * NT + tid] = 0.0f;

    const float* __restrict__ xin = x + (size_t)n * (512 * 512);

    // halo columns: stored s=0 (global col 256*half-1), s=257 (col 256*half+256)
    if (tid < 20) {
        int tr     = tid >> 1;
        int rightc = tid & 1;
        int col    = 256 * half + (rightc ? 256 : -1);
        int g      = py * 8 - 1 + tr;
        float v    = 0.0f;
        if ((unsigned)g < 512u && (unsigned)col < 512u) v = xin[g * 512 + col];
        tile[tr * R_STRIDE + (rightc ? 289 : 0)] = v;   // f(0)=0, f(257)=289
    }

    // main staging: rows py*8-1 .. py*8+8, 256 cols -> 64 float4/row, 10 rows
    const float4* __restrict__ xin4 = (const float4*)xin;
    #pragma unroll
    for (int it = 0; it < 5; it++) {
        int idx = tid + it * NT;          // 0..639
        int tr  = idx >> 6;               // tile row 0..9
        int c4  = idx & 63;               // float4 col within half, 0..63
        int g   = py * 8 - 1 + tr;        // global row
        float4 v = make_float4(0.0f, 0.0f, 0.0f, 0.0f);
        if ((unsigned)g < 512u) v = xin4[g * 128 + 64 * half + c4];
        float* rowp = &tile[tr * R_STRIDE];
        int s = c4 * 4 + 1;               // stored col, pad via f(s)=s+(s>>3)
        rowp[s + (s >> 3)]             = v.x;
        rowp[(s + 1) + ((s + 1) >> 3)] = v.y;
        rowp[(s + 2) + ((s + 2) >> 3)] = v.z;
        rowp[(s + 3) + ((s + 3) >> 3)] = v.w;
    }
    __syncthreads();

    const int cell = tid >> 2;        // local cell 0..31
    const int sub  = tid & 3;         // 0..3
    const int r0   = sub * 2;         // first tile row used (2 pixel rows/thread)
    float* __restrict__ hcol = &hist[tid];

    // Stored offset of (tile row r0+r, window col jj):
    //   s = 8*cell + jj  (jj=0 is the w-1 column of the cell's first pixel)
    //   f(s) = 9*cell + jj + (jj >= 8 ? 1 : 0)
    const int base = r0 * R_STRIDE + 9 * cell;

    // Sliding 3-column window: p = col(w-1), c = col(w), n = col(w+1)
    float a0p, a1p, c0p, c1p, a0c, a1c, c0c, c1c, a0n, a1n, c0n, c1n;
    load_col4(tile, base + 0, a0p, a1p, c0p, c1p);
    load_col4(tile, base + 1, a0c, a1c, c0c, c1c);

    #pragma unroll
    for (int i = 0; i < 8; i++) {
        const int jj = i + 2;                         // incoming column 2..9
        load_col4(tile, base + jj + (jj >= 8 ? 1 : 0), a0n, a1n, c0n, c1n);

        // gx = colA(w-1) - colA(w+1); gy = colC(w-1) + 2*colC(w) + colC(w+1)
        {
            float gx = a0p - a0n;
            float gy = c0p + 2.0f * c0c + c0n;
            accum_pixel(gx, gy, hcol);
        }
        {
            float gx = a1p - a1n;
            float gy = c1p + 2.0f * c1c + c1n;
            accum_pixel(gx, gy, hcol);
        }

        a0p = a0c; a1p = a1c; c0p = c0c; c1p = c1c;
        a0c = a0n; a1c = a1n; c0c = c0n; c1c = c1n;
    }
    __syncthreads();

    // Reduce 4 sub-threads per cell, fold col-10 into bin 0, scale by 1/64.
    // out[n*40960 + b*4096 + py*64 + 32*half + c]
    float* __restrict__ o = out + ((size_t)(n * 10) * 64 + py) * 64 + 32 * half;
    #pragma unroll
    for (int it = 0; it < 3; it++) {
        int idx = tid + it * NT;    // 0..383, use 0..319
        if (idx < 320) {
            int b = idx >> 5;       // bin 0..9
            int c = idx & 31;       // local cell
            const float* h = &hist[b * NT + c * 4];
            float s = h[0] + h[1] + h[2] + h[3];
            if (b == 0) {
                const float* h10 = &hist[10 * NT + c * 4];
                s += h10[0] + h10[1] + h10[2] + h10[3];
            }
            o[(size_t)b * (64 * 64) + c] = s * (1.0f / 64.0f);
        }
    }
}

extern "C" void kernel_launch(void* const* d_in, const int* in_sizes, int n_in,
                              void* d_out, int out_size)
{
    const float* x = (const float*)d_in[0];
    float* out     = (float*)d_out;
    dim3 grid(128, 16);
    hog_fused_kernel<<<grid, NT>>>(x, out);
}